// round 2
// baseline (speedup 1.0000x reference)
#include <cuda_runtime.h>

// Problem constants
#define NPOS 2304          // 48*48
#define PPAD 2916          // 54*54

// Scratch (device globals; no runtime allocation)
__device__ float Qbuf[2 * 4 * 2304 * 64];   // [b][g][p][c64]
__device__ float Kbuf[2 * 8 * 2916 * 32];   // [b][SL][padded pos][c32]
__device__ float Vbuf[2 * 4 * 2916 * 64];   // [b][g][padded pos][c64]

// ---------------------------------------------------------------------------
// Kernel 0: zero K/V scratch (covers zero-padding borders; interior rewritten)
// ---------------------------------------------------------------------------
__global__ void zero_pads_kernel() {
    const int nk = (2 * 8 * 2916 * 32) / 4;
    const int nv = (2 * 4 * 2916 * 64) / 4;
    float4 z = make_float4(0.f, 0.f, 0.f, 0.f);
    int stride = gridDim.x * blockDim.x;
    int i0 = blockIdx.x * blockDim.x + threadIdx.x;
    float4* k4 = (float4*)Kbuf;
    float4* v4 = (float4*)Vbuf;
    for (int i = i0; i < nk; i += stride) k4[i] = z;
    for (int i = i0; i < nv; i += stride) v4[i] = z;
}

// ---------------------------------------------------------------------------
// Kernel 1: 1x1 conv as GEMM  C[768,2304] = W[768,256] * X[256,2304] per batch
// 128(o) x 64(n) tile, 256 threads, 8x4 microtile, k-step 16.
// Epilogue transposes through smem and scatters into Q/K/V layouts (coalesced).
// ---------------------------------------------------------------------------
__global__ __launch_bounds__(256) void conv_kernel(const float* __restrict__ x,
                                                   const float* __restrict__ w) {
    __shared__ float As[16][128];
    __shared__ float Bs[16][64];
    __shared__ float Cs[128][65];

    const int b  = blockIdx.z;
    const int o0 = blockIdx.y * 128;
    const int n0 = blockIdx.x * 64;
    const int t  = threadIdx.x;
    const int tx = t & 15;      // n dim (x4)
    const int ty = t >> 4;      // o dim (x8)

    const float* Xb = x + b * (256 * NPOS);

    float acc[8][4];
#pragma unroll
    for (int i = 0; i < 8; i++)
#pragma unroll
        for (int j = 0; j < 4; j++) acc[i][j] = 0.f;

    const int arow = t >> 1, acg = t & 1;     // A loader: row 0..127, 2 col-groups
    const int bkk = t >> 4, bc4 = t & 15;     // B loader: kk 0..15, col4 0..15

    for (int c0 = 0; c0 < 256; c0 += 16) {
        float4 a0 = *(const float4*)(w + (o0 + arow) * 256 + c0 + acg * 4);
        float4 a1 = *(const float4*)(w + (o0 + arow) * 256 + c0 + 8 + acg * 4);
        float4 bv = *(const float4*)(Xb + (c0 + bkk) * NPOS + n0 + bc4 * 4);
        __syncthreads();
        As[acg * 4 + 0][arow] = a0.x;
        As[acg * 4 + 1][arow] = a0.y;
        As[acg * 4 + 2][arow] = a0.z;
        As[acg * 4 + 3][arow] = a0.w;
        As[8 + acg * 4 + 0][arow] = a1.x;
        As[8 + acg * 4 + 1][arow] = a1.y;
        As[8 + acg * 4 + 2][arow] = a1.z;
        As[8 + acg * 4 + 3][arow] = a1.w;
        *(float4*)&Bs[bkk][bc4 * 4] = bv;
        __syncthreads();
#pragma unroll
        for (int kk = 0; kk < 16; kk++) {
            float a[8], bb[4];
            *(float4*)&a[0] = *(const float4*)&As[kk][ty * 8];
            *(float4*)&a[4] = *(const float4*)&As[kk][ty * 8 + 4];
            *(float4*)&bb[0] = *(const float4*)&Bs[kk][tx * 4];
#pragma unroll
            for (int i = 0; i < 8; i++)
#pragma unroll
                for (int j = 0; j < 4; j++) acc[i][j] += a[i] * bb[j];
        }
    }

    __syncthreads();
#pragma unroll
    for (int i = 0; i < 8; i++)
#pragma unroll
        for (int j = 0; j < 4; j++) Cs[ty * 8 + i][tx * 4 + j] = acc[i][j];
    __syncthreads();

    const int lane = t & 31, wp = t >> 5;
#pragma unroll
    for (int it = 0; it < 32; it++) {
        int oc = it >> 3;            // 0..3
        int nn = it & 7;             // 0..7
        int ol = lane + 32 * oc;     // 0..127
        int nl = wp + 8 * nn;        // 0..63
        float v = Cs[ol][nl];
        int o  = o0 + ol;
        int hw = n0 + nl;
        int i2 = hw / 48, j2 = hw % 48;
        int pp = (i2 + 3) * 54 + (j2 + 3);
        if (o < 256) {
            int g = o >> 6;
            Qbuf[(((b * 4 + g) * 2304 + hw) << 6) + (o & 63)] = v;
        } else if (o < 512) {
            int ok = o - 256;
            int SL = ((ok >> 5) & 1) * 4 + (ok >> 6);
            Kbuf[(((b * 8 + SL) * PPAD + pp) << 5) + (ok & 31)] = v;
        } else {
            int ov = o - 512;
            Vbuf[(((b * 4 + (ov >> 6)) * PPAD + pp) << 6) + (ov & 63)] = v;
        }
    }
}

// ---------------------------------------------------------------------------
// Kernel 2: attention. One block per (b, g, output row i'). 384 threads.
// 8 lanes per output column j' (4-channel float4 slices).
// ---------------------------------------------------------------------------
__device__ __forceinline__ float red8(float v) {
    v += __shfl_xor_sync(0xffffffffu, v, 1);
    v += __shfl_xor_sync(0xffffffffu, v, 2);
    v += __shfl_xor_sync(0xffffffffu, v, 4);
    return v;
}
__device__ __forceinline__ float max8(float v) {
    v = fmaxf(v, __shfl_xor_sync(0xffffffffu, v, 1));
    v = fmaxf(v, __shfl_xor_sync(0xffffffffu, v, 2));
    v = fmaxf(v, __shfl_xor_sync(0xffffffffu, v, 4));
    return v;
}
__device__ __forceinline__ float dot4(float4 a, float4 b) {
    return a.x * b.x + a.y * b.y + a.z * b.z + a.w * b.w;
}

#define KT_F4 3456   // 8*54*32/4
#define VT_F4 6048   // 7*54*64/4
#define ATT_STRIDE 52

__global__ __launch_bounds__(384) void attn_kernel(const float* __restrict__ rpeh,
                                                   const float* __restrict__ rpew,
                                                   float* __restrict__ out) {
    extern __shared__ float sm[];
    float* Kt   = sm;                       // 13824 floats
    float* Vt   = sm + 13824;               // 24192 floats
    float* atts = Vt + 24192;               // 48*52 floats

    const int ip = blockIdx.x;   // output row i'
    const int g  = blockIdx.y;
    const int b  = blockIdx.z;
    const int t  = threadIdx.x;

    const int s_ = (ip >= 24) ? 1 : 0;
    const int SL = 2 * g + s_;
    const int R0 = 2 * ip - 48 * s_;

    // Stage K slab rows R0..R0+7 (contiguous) and V rows ip..ip+6 (contiguous)
    {
        const float4* ks = (const float4*)(Kbuf + (((b * 8 + SL) * PPAD + R0 * 54) << 5));
        float4* kt4 = (float4*)Kt;
        for (int i = t; i < KT_F4; i += 384) kt4[i] = ks[i];
        const float4* vsrc = (const float4*)(Vbuf + (((b * 4 + g) * PPAD + ip * 54) << 6));
        float4* vt4 = (float4*)Vt;
        for (int i = t; i < VT_F4; i += 384) vt4[i] = vsrc[i];
    }

    const int pos = t >> 3;   // j' 0..47
    const int sub = t & 7;    // lane within position

    // Load q slices (direct from gmem, coalesced)
    const float* qp = Qbuf + (((b * 4 + g) * 2304 + ip * 48 + pos) << 6);
    const float4 qlo = *(const float4*)(qp + 4 * sub);
    const float4 qhi = *(const float4*)(qp + 32 + 4 * sub);

    // RPE dot products: 7 values each for lo/hi halves
    const bool useH = (SL < 4);
    const float* rp = useH ? (rpeh + SL * 224) : (rpew + (SL - 4) * 224);
    float Rlo[7], Rhi[7];
#pragma unroll
    for (int tt = 0; tt < 7; tt++) {
        float4 rv = *(const float4*)(rp + tt * 32 + 4 * sub);
        Rlo[tt] = red8(dot4(qlo, rv));
        Rhi[tt] = red8(dot4(qhi, rv));
    }

    __syncthreads();

    const int rsel = (pos >= 24) ? 1 : 0;
    const int j0 = 2 * pos - 48 * rsel;   // even source column

    float Lreg[7] = {0.f, 0.f, 0.f, 0.f, 0.f, 0.f, 0.f};

    const float4* kt4 = (const float4*)Kt;
#pragma unroll
    for (int k = 0; k < 49; k++) {
        int wA, wB, rA, rB;
        if (k < 24)       { wA = 2 * k;      rA = 0; wB = 2 * k + 1;  rB = 0; }
        else if (k == 24) { wA = 48;         rA = 0; wB = 0;          rB = 1; }
        else              { wA = 2 * k - 49; rA = 1; wB = 2 * k - 48; rB = 1; }
        const int khA = wA / 7, kwA = wA % 7;
        const int khB = wB / 7, kwB = wB % 7;
        float4 va = kt4[(((rsel + khA) * 54 + j0 + rA + kwA) << 3) + sub];
        float4 vb = kt4[(((rsel + khB) * 54 + j0 + rB + kwB) << 3) + sub];
        float p = dot4(qlo, va) + dot4(qhi, vb);
        p = red8(p);
        float radd = useH ? (Rlo[khA] + Rhi[khB]) : (Rlo[kwA] + Rhi[kwB]);
        float L = p + radd;
        if ((k & 7) == sub) Lreg[k >> 3] = L;
    }

    // Softmax over 49, values distributed k = sub + 8*i across the 8 lanes
    const int nk = (sub == 0) ? 7 : 6;
    float m = -1e30f;
#pragma unroll
    for (int i = 0; i < 7; i++)
        if (i < nk) m = fmaxf(m, Lreg[i]);
    m = max8(m);
    float ssum = 0.f;
#pragma unroll
    for (int i = 0; i < 7; i++)
        if (i < nk) { Lreg[i] = __expf(Lreg[i] - m); ssum += Lreg[i]; }
    ssum = red8(ssum);
    float inv = 1.0f / ssum;
#pragma unroll
    for (int i = 0; i < 7; i++) {
        int k = sub + 8 * i;
        if (k < 49) atts[pos * ATT_STRIDE + k] = Lreg[i] * inv;
    }
    __syncwarp();

    // AV: lane accumulates channels {4sub..4sub+3} and {32+4sub..}
    float4 acc0 = make_float4(0.f, 0.f, 0.f, 0.f);
    float4 acc1 = make_float4(0.f, 0.f, 0.f, 0.f);
    const float4* vt4 = (const float4*)Vt;
#pragma unroll
    for (int k = 0; k < 49; k++) {
        const int kh = k / 7, kw = k % 7;
        float a = atts[pos * ATT_STRIDE + k];
        const float4* vv = vt4 + (((kh * 54 + pos + kw) << 4) + sub);
        float4 v0 = vv[0];
        float4 v1 = vv[8];
        acc0.x += a * v0.x; acc0.y += a * v0.y; acc0.z += a * v0.z; acc0.w += a * v0.w;
        acc1.x += a * v1.x; acc1.y += a * v1.y; acc1.z += a * v1.z; acc1.w += a * v1.w;
    }

    // Write out: out[b][g*64+c][ip][pos]
    float* op = out + (b * 256 + g * 64) * NPOS + ip * 48 + pos;
    op[(4 * sub + 0) * NPOS] = acc0.x;
    op[(4 * sub + 1) * NPOS] = acc0.y;
    op[(4 * sub + 2) * NPOS] = acc0.z;
    op[(4 * sub + 3) * NPOS] = acc0.w;
    op[(32 + 4 * sub + 0) * NPOS] = acc1.x;
    op[(32 + 4 * sub + 1) * NPOS] = acc1.y;
    op[(32 + 4 * sub + 2) * NPOS] = acc1.z;
    op[(32 + 4 * sub + 3) * NPOS] = acc1.w;
}

// ---------------------------------------------------------------------------
extern "C" void kernel_launch(void* const* d_in, const int* in_sizes, int n_in,
                              void* d_out, int out_size) {
    const float* x  = (const float*)d_in[0];
    const float* w  = (const float*)d_in[1];
    const float* rh = (const float*)d_in[2];
    const float* rw = (const float*)d_in[3];
    float* out = (float*)d_out;

    zero_pads_kernel<<<512, 256>>>();

    dim3 gc(36, 6, 2);
    conv_kernel<<<gc, 256>>>(x, w);

    const int SMEM = (13824 + 24192 + 48 * ATT_STRIDE) * 4;
    cudaFuncSetAttribute(attn_kernel, cudaFuncAttributeMaxDynamicSharedMemorySize, SMEM);
    dim3 ga(48, 4, 2);
    attn_kernel<<<ga, 384, SMEM>>>(rh, rw, out);
}